// round 5
// baseline (speedup 1.0000x reference)
#include <cuda_runtime.h>
#include <cstdint>

// Problem dims
#define BZc   8
#define NUMc  1024
#define NAc   64
#define FDc   128

typedef unsigned long long u64;
typedef unsigned int u32;

// ---------------- helpers ----------------
__device__ __forceinline__ float tanha(float x) {           // HW approx, hidden only
    float y; asm("tanh.approx.f32 %0, %1;" : "=f"(y) : "f"(x)); return y;
}
// Fast precise tanh: ex2 + rcp + 1 Newton step (~4e-7). Head/logit path.
__device__ __forceinline__ float tanhp(float x) {
    float t; asm("ex2.approx.f32 %0, %1;" : "=f"(t) : "f"(x * 2.8853900817779268f));
    float d = 1.0f + t;
    float r; asm("rcp.approx.f32 %0, %1;" : "=f"(r) : "f"(d));
    r = fmaf(fmaf(-d, r, 1.0f), r, r);
    return fmaf(-2.0f, r, 1.0f);
}
__device__ __forceinline__ float to_tf32(float x) {
    float y; asm("cvt.rna.tf32.f32 %0, %1;" : "=f"(y) : "f"(x)); return y;
}
__device__ __forceinline__ void mma_tf32(float d[4],
    u32 a0, u32 a1, u32 a2, u32 a3, u32 b0, u32 b1)
{
    asm("mma.sync.aligned.m16n8k8.row.col.f32.tf32.tf32.f32 "
        "{%0,%1,%2,%3}, {%4,%5,%6,%7}, {%8,%9}, {%0,%1,%2,%3};"
        : "+f"(d[0]), "+f"(d[1]), "+f"(d[2]), "+f"(d[3])
        : "r"(a0), "r"(a1), "r"(a2), "r"(a3), "r"(b0), "r"(b1));
}

// ---------------- folded weight storage ----------------
__device__ float g_Wt[64 * FDc];   // tf32 folded layer-1 [o][c]
__device__ float g_c1[64];
__device__ float g_M2[32 * 80];    // tf32 folded agg matrix [o][k]: k<64 Mf, k>=64 Ms
__device__ float g_ca[32];
__device__ float g_B1[8][4];
__device__ float g_d1[8];
__device__ float g_B2[16][8];
__device__ float g_d2[16];
__device__ float g_Wa2[32];
__device__ float g_ba2s;

// ---------------- weight folding kernel ----------------
__global__ void disarm_prep(
    const float* __restrict__ Wf1, const float* __restrict__ bf1,
    const float* __restrict__ gf1, const float* __restrict__ btf1,
    const float* __restrict__ Wf2, const float* __restrict__ bf2,
    const float* __restrict__ Ws1, const float* __restrict__ bs1,
    const float* __restrict__ gs1, const float* __restrict__ bts1,
    const float* __restrict__ Ws2, const float* __restrict__ bs2,
    const float* __restrict__ gs2, const float* __restrict__ bts2,
    const float* __restrict__ Ws3, const float* __restrict__ bs3,
    const float* __restrict__ Wa1, const float* __restrict__ ba1,
    const float* __restrict__ ga1, const float* __restrict__ bta1,
    const float* __restrict__ Wa2, const float* __restrict__ ba2)
{
    const float inv = rsqrtf(1.0f + 1e-5f);
    const int t = threadIdx.x;
    const int nt = blockDim.x;

    for (int i = t; i < 64 * FDc; i += nt) {
        int o = i >> 7, c = i & 127;
        g_Wt[i] = to_tf32(gf1[o] * inv * Wf1[o * FDc + c]);
    }
    for (int i = t; i < 64; i += nt) g_c1[i] = gf1[i]*inv*bf1[i] + btf1[i];

    // M2[o][k]: k<64 -> ga1[o]*inv*sum_j Wa1[o][32+j]*Wf2[j][k]
    //           k>=64 -> ga1[o]*inv*sum_m Wa1[o][m]*Ws3[m][k-64]
    for (int i = t; i < 32 * 80; i += nt) {
        int o = i / 80, k = i - 80 * o;
        float acc = 0.0f;
        if (k < 64) {
            for (int j = 0; j < 32; ++j) acc += Wa1[o*64 + 32 + j] * Wf2[j*64 + k];
        } else {
            for (int m = 0; m < 32; ++m) acc += Wa1[o*64 + m] * Ws3[m*16 + (k - 64)];
        }
        g_M2[i] = to_tf32(ga1[o] * inv * acc);
    }
    if (t < 32) {
        float acc = 0.0f;
        for (int j = 0; j < 32; ++j) acc += Wa1[t*64 + 32 + j] * bf2[j];
        for (int m = 0; m < 32; ++m) acc += Wa1[t*64 + m] * bs3[m];
        g_ca[t] = ga1[t]*inv*(acc + ba1[t]) + bta1[t];
    }
    if (t < 8) {
        for (int i = 0; i < 3; ++i) g_B1[t][i] = gs1[t]*inv*Ws1[t*3 + i];
        g_B1[t][3] = 0.0f;
        g_d1[t] = gs1[t]*inv*bs1[t] + bts1[t];
    }
    if (t < 16) {
        for (int i = 0; i < 8; ++i) g_B2[t][i] = gs2[t]*inv*Ws2[t*8 + i];
        g_d2[t] = gs2[t]*inv*bs2[t] + bts2[t];
    }
    if (t < 32) g_Wa2[t] = Wa2[t];
    if (t == 0) g_ba2s = ba2[0];
}

// ---------------- smem layout (bytes) ----------------
#define XSTRIDE  72     // floats/row, conflict-free B frags
#define CSTRIDE  72
#define M2S      84     // conflict-free A2 frag loads
#define SM_X     0                          // 128*72*4 = 36864
#define SM_C     36864                      // 80*72*4  = 23040
#define SM_M2    (SM_C + 23040)             // 32*84*4  = 10752
#define SM_PART  (SM_M2 + 10752)            // 2*64*4   = 512
#define SM_C1    (SM_PART + 512)            // 256
#define SM_CA    (SM_C1 + 256)              // 128
#define SM_WA2   (SM_CA + 128)              // 128
#define SM_B1    (SM_WA2 + 128)             // 128
#define SM_D1    (SM_B1 + 128)              // 32
#define SM_B2    (SM_D1 + 32)               // 512
#define SM_D2    (SM_B2 + 512)              // 64
#define SM_BA2   (SM_D2 + 64)               // 16
#define SM_TOTAL (SM_BA2 + 16)

// ---------------- main fused kernel ----------------
// One (b,p) group per CTA, 256 threads = 8 warps. All warps work all stages:
//   mma1: H[64x64] = W1 @ X      (warp (wM,wN): rows 16wM.., anchors 32wN..)
//   epi1: tanh -> C[0:64][a]; spatial SIMT -> C[64:80][a]
//   mma2: A2[32x64] = M2 @ C     (warp (m,nt): rows 16m.., anchor tiles 2nt..)
//   epi2: Wa2*tanh(A2+ca) partials -> shuffle reduce -> sPart[2][64]
//   tail: warp 0 softmax + min-max norm
__global__ void __launch_bounds__(256, 2) disarm_mma(
    const float* __restrict__ loc, const float* __restrict__ feat,
    float* __restrict__ out)
{
    extern __shared__ char smem[];
    float* sX    = (float*)(smem + SM_X);
    float* sC    = (float*)(smem + SM_C);
    float* sM2   = (float*)(smem + SM_M2);
    float (*sPart)[64] = (float (*)[64])(smem + SM_PART);
    float* sc1   = (float*)(smem + SM_C1);
    float* sca   = (float*)(smem + SM_CA);
    float* sWa2v = (float*)(smem + SM_WA2);
    float (*sB1)[4] = (float (*)[4])(smem + SM_B1);
    float* sd1   = (float*)(smem + SM_D1);
    float (*sB2)[8] = (float (*)[8])(smem + SM_B2);
    float* sd2   = (float*)(smem + SM_D2);
    float* sba2  = (float*)(smem + SM_BA2);

    const int tid  = threadIdx.x;
    const int warp = tid >> 5;
    const int lane = tid & 31;
    const int g8   = lane >> 2;
    const int t4   = lane & 3;
    const int wM   = warp >> 1;   // mma1 row tile (0..3)
    const int wN   = warp & 1;    // mma1 anchor half (0..1)

    const int gp = blockIdx.x;
    const int b  = gp >> 10;
    const int p  = gp & 1023;
    const size_t cs = (size_t)NUMc * NAc;

    // ---- A1 fragments from global (L1-cached) ----
    u32 A[64];
    {
        const float* W0 = g_Wt + (16 * wM + g8) * FDc;
        const float* W8 = W0 + 8 * FDc;
        #pragma unroll
        for (int k = 0; k < 16; ++k) {
            int c0 = 8 * k + t4;
            A[4*k+0] = __float_as_uint(__ldg(W0 + c0));
            A[4*k+1] = __float_as_uint(__ldg(W8 + c0));
            A[4*k+2] = __float_as_uint(__ldg(W0 + c0 + 4));
            A[4*k+3] = __float_as_uint(__ldg(W8 + c0 + 4));
        }
    }

    // ---- stage M2 + small weights + X tile ----
    for (int i = tid; i < 32 * 80; i += 256) {
        int r = i / 80, c = i - 80 * r;
        sM2[r * M2S + c] = g_M2[i];
    }
    if (tid < 64) sc1[tid] = g_c1[tid];
    if (tid < 32) { sca[tid] = g_ca[tid]; sWa2v[tid] = g_Wa2[tid]; }
    if (tid < 32) sB1[tid>>2][tid&3] = g_B1[tid>>2][tid&3];
    if (tid < 8)  sd1[tid] = g_d1[tid];
    if (tid >= 128 && tid < 256) sB2[(tid-128)>>3][(tid-128)&7] = g_B2[(tid-128)>>3][(tid-128)&7];
    if (tid < 16) sd2[tid] = g_d2[tid];
    if (tid == 0) sba2[0] = g_ba2s;
    {
        const float* fbase = feat + (size_t)b * FDc * cs + (size_t)p * NAc;
        for (int i = tid; i < FDc * 16; i += 256) {
            int c = i >> 4, v = i & 15;
            float4 x = __ldg((const float4*)(fbase + (size_t)c * cs) + v);
            x.x = to_tf32(x.x); x.y = to_tf32(x.y);
            x.z = to_tf32(x.z); x.w = to_tf32(x.w);
            *(float4*)(sX + c * XSTRIDE + 4 * v) = x;
        }
    }
    __syncthreads();

    // ---- mma1: 64 mma per warp ----
    float D[4][4];
    #pragma unroll
    for (int n = 0; n < 4; ++n) { D[n][0]=0.f; D[n][1]=0.f; D[n][2]=0.f; D[n][3]=0.f; }
    {
        #pragma unroll
        for (int k = 0; k < 16; ++k) {
            const float* r0 = sX + (8*k + t4) * XSTRIDE + 32*wN + g8;
            const float* r4 = r0 + 4 * XSTRIDE;
            #pragma unroll
            for (int n = 0; n < 4; ++n) {
                u32 b0 = __float_as_uint(r0[8*n]);
                u32 b1 = __float_as_uint(r4[8*n]);
                mma_tf32(D[n], A[4*k], A[4*k+1], A[4*k+2], A[4*k+3], b0, b1);
            }
        }
    }

    // ---- spatial branch -> C rows 64..79 (no alias with sX; safe pre-sync) ----
    {
        const int a  = tid & 63;
        const int os = tid >> 6;                 // 4 outputs per thread
        const float* lp = loc + (((size_t)(b*NUMc + p))*NAc + a) * 3;
        const float l0 = lp[0], l1 = lp[1], l2 = lp[2];
        float s1v[8];
        #pragma unroll
        for (int j = 0; j < 8; ++j)
            s1v[j] = tanha(sB1[j][0]*l0 + sB1[j][1]*l1 + sB1[j][2]*l2 + sd1[j]);
        #pragma unroll
        for (int jj = 0; jj < 4; ++jj) {
            const int o = 4*os + jj;
            float acc = sd2[o];
            #pragma unroll
            for (int i = 0; i < 8; ++i) acc += sB2[o][i] * s1v[i];
            sC[(64 + o) * CSTRIDE + a] = to_tf32(tanha(acc));
        }
    }

    // ---- epi1: tanh(H + c1) -> C rows 0..63 (tf32-rounded) ----
    {
        const int ro = 16*wM + g8;
        const float c1a = sc1[ro];
        const float c1b = sc1[ro + 8];
        float* cr0 = sC + ro * CSTRIDE;
        float* cr8 = cr0 + 8 * CSTRIDE;
        #pragma unroll
        for (int n = 0; n < 4; ++n) {
            const int c0 = 32*wN + 8*n + 2*t4;
            cr0[c0]     = to_tf32(tanha(D[n][0] + c1a));
            cr0[c0 + 1] = to_tf32(tanha(D[n][1] + c1a));
            cr8[c0]     = to_tf32(tanha(D[n][2] + c1b));
            cr8[c0 + 1] = to_tf32(tanha(D[n][3] + c1b));
        }
    }
    __syncthreads();

    // ---- mma2: A2[32x64] = M2[32x80] @ C[80x64]; 20 mma per warp ----
    const int m  = warp & 1;      // row half
    const int nt = warp >> 1;     // anchor 16-col tile (0..3)
    u32 A2[40];
    {
        const float* M0 = sM2 + (16*m + g8) * M2S;
        const float* M8 = M0 + 8 * M2S;
        #pragma unroll
        for (int k = 0; k < 10; ++k) {
            int c0 = 8*k + t4;
            A2[4*k+0] = __float_as_uint(M0[c0]);
            A2[4*k+1] = __float_as_uint(M8[c0]);
            A2[4*k+2] = __float_as_uint(M0[c0 + 4]);
            A2[4*k+3] = __float_as_uint(M8[c0 + 4]);
        }
    }
    float D2[2][4];
    D2[0][0]=0.f; D2[0][1]=0.f; D2[0][2]=0.f; D2[0][3]=0.f;
    D2[1][0]=0.f; D2[1][1]=0.f; D2[1][2]=0.f; D2[1][3]=0.f;
    {
        #pragma unroll
        for (int k = 0; k < 10; ++k) {
            const float* r0 = sC + (8*k + t4) * CSTRIDE + 16*nt + g8;
            const float* r4 = r0 + 4 * CSTRIDE;
            u32 b0 = __float_as_uint(r0[0]);
            u32 b1 = __float_as_uint(r4[0]);
            mma_tf32(D2[0], A2[4*k], A2[4*k+1], A2[4*k+2], A2[4*k+3], b0, b1);
            b0 = __float_as_uint(r0[8]);
            b1 = __float_as_uint(r4[8]);
            mma_tf32(D2[1], A2[4*k], A2[4*k+1], A2[4*k+2], A2[4*k+3], b0, b1);
        }
    }

    // ---- epi2: head partials w[o]*tanh(a2+ca) reduced over rows ----
    {
        const int ro = 16*m + g8;
        const float wa  = sWa2v[ro],   wb  = sWa2v[ro + 8];
        const float caa = sca[ro],     cab = sca[ro + 8];
        float p0 = wa * tanhp(D2[0][0] + caa) + wb * tanhp(D2[0][2] + cab);
        float p1 = wa * tanhp(D2[0][1] + caa) + wb * tanhp(D2[0][3] + cab);
        float p2 = wa * tanhp(D2[1][0] + caa) + wb * tanhp(D2[1][2] + cab);
        float p3 = wa * tanhp(D2[1][1] + caa) + wb * tanhp(D2[1][3] + cab);
        const unsigned m32 = 0xffffffffu;
        #pragma unroll
        for (int off = 4; off <= 16; off <<= 1) {
            p0 += __shfl_xor_sync(m32, p0, off);
            p1 += __shfl_xor_sync(m32, p1, off);
            p2 += __shfl_xor_sync(m32, p2, off);
            p3 += __shfl_xor_sync(m32, p3, off);
        }
        if (g8 == 0) {
            const int c0 = 16*nt + 2*t4;
            sPart[m][c0]     = p0;
            sPart[m][c0 + 1] = p1;
            sPart[m][c0 + 8] = p2;
            sPart[m][c0 + 9] = p3;
        }
    }
    __syncthreads();

    // ---- tail: warp 0 softmax over 64 anchors + min-max norm ----
    if (warp != 0) return;
    const int a0 = lane, a1 = lane + 32;
    const float lg0 = tanhp(sPart[0][a0] + sPart[1][a0] + sba2[0]);
    const float lg1 = tanhp(sPart[0][a1] + sPart[1][a1] + sba2[0]);

    const unsigned m32 = 0xffffffffu;
    float mx = fmaxf(lg0, lg1);
    float mn = fminf(lg0, lg1);
    #pragma unroll
    for (int off = 16; off > 0; off >>= 1) {
        mx = fmaxf(mx, __shfl_xor_sync(m32, mx, off));
        mn = fminf(mn, __shfl_xor_sync(m32, mn, off));
    }
    const float e0 = expf(lg0 - mx);
    const float e1 = expf(lg1 - mx);
    float ssum = e0 + e1;
    #pragma unroll
    for (int off = 16; off > 0; off >>= 1) ssum += __shfl_xor_sync(m32, ssum, off);
    const float invs = 1.0f / ssum;

    const float w0  = e0 * invs;
    const float w1  = e1 * invs;
    const float wmn = expf(mn - mx) * invs;
    const float wmx = invs;
    const float k   = (1.0f + 1e-6f) / (wmx - wmn + 1e-6f);

    float* ob = out + (size_t)gp * NAc;
    float* on = ob + (size_t)BZc * NUMc * NAc;
    ob[a0] = w0;
    ob[a1] = w1;
    on[a0] = k * (w0 - wmn);
    on[a1] = k * (w1 - wmn);
}

// ---------------- launch ----------------
extern "C" void kernel_launch(void* const* d_in, const int* in_sizes, int n_in,
                              void* d_out, int out_size)
{
    const float* loc  = (const float*)d_in[0];
    const float* feat = (const float*)d_in[1];

    disarm_prep<<<1, 256>>>(
        (const float*)d_in[2],  (const float*)d_in[3],  (const float*)d_in[4],  (const float*)d_in[5],
        (const float*)d_in[6],  (const float*)d_in[7],
        (const float*)d_in[8],  (const float*)d_in[9],  (const float*)d_in[10], (const float*)d_in[11],
        (const float*)d_in[12], (const float*)d_in[13], (const float*)d_in[14], (const float*)d_in[15],
        (const float*)d_in[16], (const float*)d_in[17],
        (const float*)d_in[18], (const float*)d_in[19], (const float*)d_in[20], (const float*)d_in[21],
        (const float*)d_in[22], (const float*)d_in[23]);

    static int smem_set = 0;
    if (!smem_set) {
        cudaFuncSetAttribute(disarm_mma,
                             cudaFuncAttributeMaxDynamicSharedMemorySize, SM_TOTAL);
        smem_set = 1;
    }
    disarm_mma<<<BZc * NUMc, 256, SM_TOTAL>>>(loc, feat, (float*)d_out);
}

// round 6
// speedup vs baseline: 2.3023x; 2.3023x over previous
#include <cuda_runtime.h>
#include <cstdint>

// Problem dims
#define BZc   8
#define NUMc  1024
#define NAc   64
#define FDc   128
#define GRPS  8          // (b,p) groups per CTA

typedef unsigned long long u64;
typedef unsigned int u32;

// ---------------- helpers ----------------
__device__ __forceinline__ float tanha(float x) {           // HW approx, hidden only
    float y; asm("tanh.approx.f32 %0, %1;" : "=f"(y) : "f"(x)); return y;
}
// Fast precise tanh: ex2 + rcp + 1 Newton step (~4e-7). Head/logit path.
__device__ __forceinline__ float tanhp(float x) {
    float t; asm("ex2.approx.f32 %0, %1;" : "=f"(t) : "f"(x * 2.8853900817779268f));
    float d = 1.0f + t;
    float r; asm("rcp.approx.f32 %0, %1;" : "=f"(r) : "f"(d));
    r = fmaf(fmaf(-d, r, 1.0f), r, r);
    return fmaf(-2.0f, r, 1.0f);
}
__device__ __forceinline__ float to_tf32(float x) {
    float y; asm("cvt.rna.tf32.f32 %0, %1;" : "=f"(y) : "f"(x)); return y;
}
__device__ __forceinline__ void mma_tf32(float d[4],
    u32 a0, u32 a1, u32 a2, u32 a3, u32 b0, u32 b1)
{
    asm("mma.sync.aligned.m16n8k8.row.col.f32.tf32.tf32.f32 "
        "{%0,%1,%2,%3}, {%4,%5,%6,%7}, {%8,%9}, {%0,%1,%2,%3};"
        : "+f"(d[0]), "+f"(d[1]), "+f"(d[2]), "+f"(d[3])
        : "r"(a0), "r"(a1), "r"(a2), "r"(a3), "r"(b0), "r"(b1));
}
__device__ __forceinline__ void cpa16(u32 dst, const void* src) {
    asm volatile("cp.async.cg.shared.global [%0], [%1], 16;" :: "r"(dst), "l"(src));
}
#define CP_COMMIT() asm volatile("cp.async.commit_group;")
#define CP_WAIT0()  asm volatile("cp.async.wait_group 0;")

// ---------------- folded weight storage (fragment layouts) ----------------
// A1 fragments: [tile(4)][k(16)][lane(32)] float4 — coalesced LDG.128 per k.
__device__ float4 g_WtF[4 * 16 * 32];
// M2 fragments: [m(2)][k(10)][lane(32)] float4
__device__ float4 g_M2F[2 * 10 * 32];
__device__ float g_c1[64];
__device__ float g_ca[32];
__device__ float g_B1[8][4];
__device__ float g_d1[8];
__device__ float g_B2[16][8];
__device__ float g_d2[16];
__device__ float g_Wa2[32];
__device__ float g_ba2s;

// ---------------- weight folding kernel ----------------
__global__ void disarm_prep(
    const float* __restrict__ Wf1, const float* __restrict__ bf1,
    const float* __restrict__ gf1, const float* __restrict__ btf1,
    const float* __restrict__ Wf2, const float* __restrict__ bf2,
    const float* __restrict__ Ws1, const float* __restrict__ bs1,
    const float* __restrict__ gs1, const float* __restrict__ bts1,
    const float* __restrict__ Ws2, const float* __restrict__ bs2,
    const float* __restrict__ gs2, const float* __restrict__ bts2,
    const float* __restrict__ Ws3, const float* __restrict__ bs3,
    const float* __restrict__ Wa1, const float* __restrict__ ba1,
    const float* __restrict__ ga1, const float* __restrict__ bta1,
    const float* __restrict__ Wa2, const float* __restrict__ ba2)
{
    const float inv = rsqrtf(1.0f + 1e-5f);
    const int t = threadIdx.x;
    const int nt = blockDim.x;

    // folded layer-1 value (tf32)
    auto wt = [&](int r, int c) -> float {
        return to_tf32(gf1[r] * inv * Wf1[r * FDc + c]);
    };
    // A1 fragments
    for (int i = t; i < 4 * 16 * 32; i += nt) {
        int tile = i >> 9, k = (i >> 5) & 15, lane = i & 31;
        int g8 = lane >> 2, t4 = lane & 3;
        int r = 16 * tile + g8, c = 8 * k + t4;
        g_WtF[i] = make_float4(wt(r, c), wt(r + 8, c), wt(r, c + 4), wt(r + 8, c + 4));
    }
    // folded agg value M2[o][kk] (tf32): kk<64 feature, kk>=64 spatial
    auto m2 = [&](int o, int kk) -> float {
        float acc = 0.0f;
        if (kk < 64) {
            for (int j = 0; j < 32; ++j) acc += Wa1[o*64 + 32 + j] * Wf2[j*64 + kk];
        } else {
            for (int m = 0; m < 32; ++m) acc += Wa1[o*64 + m] * Ws3[m*16 + (kk - 64)];
        }
        return to_tf32(ga1[o] * inv * acc);
    };
    // M2 fragments
    for (int i = t; i < 2 * 10 * 32; i += nt) {
        int m = i / (10 * 32), k = (i / 32) % 10, lane = i & 31;
        int g8 = lane >> 2, t4 = lane & 3;
        int r = 16 * m + g8, c = 8 * k + t4;
        g_M2F[i] = make_float4(m2(r, c), m2(r + 8, c), m2(r, c + 4), m2(r + 8, c + 4));
    }
    for (int i = t; i < 64; i += nt) g_c1[i] = gf1[i]*inv*bf1[i] + btf1[i];
    if (t < 32) {
        float acc = 0.0f;
        for (int j = 0; j < 32; ++j) acc += Wa1[t*64 + 32 + j] * bf2[j];
        for (int m = 0; m < 32; ++m) acc += Wa1[t*64 + m] * bs3[m];
        g_ca[t] = ga1[t]*inv*(acc + ba1[t]) + bta1[t];
    }
    if (t < 8) {
        for (int i = 0; i < 3; ++i) g_B1[t][i] = gs1[t]*inv*Ws1[t*3 + i];
        g_B1[t][3] = 0.0f;
        g_d1[t] = gs1[t]*inv*bs1[t] + bts1[t];
    }
    if (t < 16) {
        for (int i = 0; i < 8; ++i) g_B2[t][i] = gs2[t]*inv*Ws2[t*8 + i];
        g_d2[t] = gs2[t]*inv*bs2[t] + bts2[t];
    }
    if (t < 32) g_Wa2[t] = Wa2[t];
    if (t == 0) g_ba2s = ba2[0];
}

// ---------------- smem layout (bytes) ----------------
#define XSTRIDE  72                 // floats/row, conflict-free B frags, 16B-aligned
#define XBUF     (FDc * XSTRIDE * 4)        // 36864 per buffer
#define CSTRIDE  72
#define SM_X     0                          // 2 buffers: 73728
#define SM_C     (2 * XBUF)                 // 80*72*4 = 23040
#define SM_M2F   (SM_C + 23040)             // 640 float4 = 10240
#define SM_PART  (SM_M2F + 10240)           // 2*64*4 = 512
#define SM_C1    (SM_PART + 512)            // 256
#define SM_CA    (SM_C1 + 256)              // 128
#define SM_WA2   (SM_CA + 128)              // 128
#define SM_B1    (SM_WA2 + 128)             // 128
#define SM_D1    (SM_B1 + 128)              // 32
#define SM_B2    (SM_D1 + 32)               // 512
#define SM_D2    (SM_B2 + 512)              // 64
#define SM_BA2   (SM_D2 + 64)               // 16
#define SM_TOTAL (SM_BA2 + 16)

// ---------------- main fused kernel ----------------
// 8 (b,p) groups per CTA, 256 threads. A1 frags persistent in registers;
// X tiles cp.async double-buffered; M2 frags staged to smem once.
__global__ void __launch_bounds__(256, 2) disarm_mma(
    const float* __restrict__ loc, const float* __restrict__ feat,
    float* __restrict__ out)
{
    extern __shared__ char smem[];
    float* sX    = (float*)(smem + SM_X);
    float* sC    = (float*)(smem + SM_C);
    float4* sM2F = (float4*)(smem + SM_M2F);
    float (*sPart)[64] = (float (*)[64])(smem + SM_PART);
    float* sc1   = (float*)(smem + SM_C1);
    float* sca   = (float*)(smem + SM_CA);
    float* sWa2v = (float*)(smem + SM_WA2);
    float (*sB1)[4] = (float (*)[4])(smem + SM_B1);
    float* sd1   = (float*)(smem + SM_D1);
    float (*sB2)[8] = (float (*)[8])(smem + SM_B2);
    float* sd2   = (float*)(smem + SM_D2);
    float* sba2  = (float*)(smem + SM_BA2);

    u32 sbase;
    asm("{.reg .u64 t; cvta.to.shared.u64 t, %1; cvt.u32.u64 %0, t;}"
        : "=r"(sbase) : "l"(smem));

    const int tid  = threadIdx.x;
    const int warp = tid >> 5;
    const int lane = tid & 31;
    const int g8   = lane >> 2;
    const int t4   = lane & 3;
    const int wM   = warp >> 1;   // mma1 row tile
    const int wN   = warp & 1;    // mma1 anchor half
    const int m    = warp & 1;    // mma2 row half
    const int nt   = warp >> 1;   // mma2 anchor 16-col tile

    const size_t cs = (size_t)NUMc * NAc;
    const int gp0 = blockIdx.x * GRPS;

    // ---- issue cp.async for group 0's X tile ----
    {
        const int b = gp0 >> 10, p = gp0 & 1023;
        const float* fbase = feat + (size_t)b * FDc * cs + (size_t)p * NAc;
        for (int i = tid; i < FDc * 16; i += 256) {
            int r = i >> 4, c16 = i & 15;
            cpa16(sbase + SM_X + r * (XSTRIDE*4) + c16 * 16,
                  fbase + (size_t)r * cs + c16 * 4);
        }
        CP_COMMIT();
    }

    // ---- persistent A1 fragments (coalesced LDG.128, once per CTA) ----
    u32 A[64];
    {
        const float4* aw = g_WtF + (size_t)wM * 16 * 32 + lane;
        #pragma unroll
        for (int k = 0; k < 16; ++k) {
            float4 v = __ldg(aw + k * 32);
            A[4*k+0] = __float_as_uint(v.x);
            A[4*k+1] = __float_as_uint(v.y);
            A[4*k+2] = __float_as_uint(v.z);
            A[4*k+3] = __float_as_uint(v.w);
        }
    }

    // ---- stage M2 fragments + small weights (once per CTA) ----
    for (int i = tid; i < 640; i += 256) sM2F[i] = g_M2F[i];
    if (tid < 64) sc1[tid] = g_c1[tid];
    if (tid < 32) { sca[tid] = g_ca[tid]; sWa2v[tid] = g_Wa2[tid]; }
    if (tid < 32) sB1[tid>>2][tid&3] = g_B1[tid>>2][tid&3];
    if (tid < 8)  sd1[tid] = g_d1[tid];
    if (tid >= 128 && tid < 256) sB2[(tid-128)>>3][(tid-128)&7] = g_B2[(tid-128)>>3][(tid-128)&7];
    if (tid < 16) sd2[tid] = g_d2[tid];
    if (tid == 0) sba2[0] = g_ba2s;

    const int sa   = tid & 63;       // spatial anchor
    const int sos  = tid >> 6;       // spatial output slice (4 outputs)

    #pragma unroll 1
    for (int g = 0; g < GRPS; ++g) {
        const int gp = gp0 + g;
        const int b  = gp >> 10;
        const int p  = gp & 1023;
        float* xb = sX + (g & 1) * (FDc * XSTRIDE);

        CP_WAIT0();
        __syncthreads();            // X[g] visible; sC free (mma2[g-1] done)

        // prefetch X for group g+1 into the other buffer
        if (g + 1 < GRPS) {
            const int gp1 = gp + 1;
            const int b1 = gp1 >> 10, p1 = gp1 & 1023;
            const float* fb1 = feat + (size_t)b1 * FDc * cs + (size_t)p1 * NAc;
            u32 dst = sbase + SM_X + ((g + 1) & 1) * XBUF;
            for (int i = tid; i < FDc * 16; i += 256) {
                int r = i >> 4, c16 = i & 15;
                cpa16(dst + r * (XSTRIDE*4) + c16 * 16,
                      fb1 + (size_t)r * cs + c16 * 4);
            }
            CP_COMMIT();
        }

        // early loc load (latency hides under mma1)
        const float* lp = loc + (((size_t)(b*NUMc + p))*NAc + sa) * 3;
        const float l0 = __ldg(lp), l1 = __ldg(lp + 1), l2 = __ldg(lp + 2);

        // ---- mma1: H tile = W1 @ X (64 mma/warp) ----
        float D[4][4];
        #pragma unroll
        for (int n = 0; n < 4; ++n) { D[n][0]=0.f; D[n][1]=0.f; D[n][2]=0.f; D[n][3]=0.f; }
        #pragma unroll
        for (int k = 0; k < 16; ++k) {
            const float* r0 = xb + (8*k + t4) * XSTRIDE + 32*wN + g8;
            const float* r4 = r0 + 4 * XSTRIDE;
            #pragma unroll
            for (int n = 0; n < 4; ++n) {
                u32 b0 = __float_as_uint(r0[8*n]);
                u32 b1 = __float_as_uint(r4[8*n]);
                mma_tf32(D[n], A[4*k], A[4*k+1], A[4*k+2], A[4*k+3], b0, b1);
            }
        }

        // ---- spatial branch -> C rows 64..79 ----
        {
            float s1v[8];
            #pragma unroll
            for (int j = 0; j < 8; ++j)
                s1v[j] = tanha(sB1[j][0]*l0 + sB1[j][1]*l1 + sB1[j][2]*l2 + sd1[j]);
            #pragma unroll
            for (int jj = 0; jj < 4; ++jj) {
                const int o = 4*sos + jj;
                float acc = sd2[o];
                #pragma unroll
                for (int i = 0; i < 8; ++i) acc += sB2[o][i] * s1v[i];
                sC[(64 + o) * CSTRIDE + sa] = to_tf32(tanha(acc));
            }
        }

        // ---- epi1: tanh(H + c1) -> C rows 0..63 ----
        {
            const int ro = 16*wM + g8;
            const float c1a = sc1[ro];
            const float c1b = sc1[ro + 8];
            float* cr0 = sC + ro * CSTRIDE;
            float* cr8 = cr0 + 8 * CSTRIDE;
            #pragma unroll
            for (int n = 0; n < 4; ++n) {
                const int c0 = 32*wN + 8*n + 2*t4;
                cr0[c0]     = to_tf32(tanha(D[n][0] + c1a));
                cr0[c0 + 1] = to_tf32(tanha(D[n][1] + c1a));
                cr8[c0]     = to_tf32(tanha(D[n][2] + c1b));
                cr8[c0 + 1] = to_tf32(tanha(D[n][3] + c1b));
            }
        }
        __syncthreads();

        // ---- mma2: A2[32x64] = M2 @ C (20 mma/warp) ----
        float D2[2][4];
        D2[0][0]=0.f; D2[0][1]=0.f; D2[0][2]=0.f; D2[0][3]=0.f;
        D2[1][0]=0.f; D2[1][1]=0.f; D2[1][2]=0.f; D2[1][3]=0.f;
        #pragma unroll
        for (int k = 0; k < 10; ++k) {
            float4 av = sM2F[(m * 10 + k) * 32 + lane];
            const u32 a0 = __float_as_uint(av.x), a1 = __float_as_uint(av.y);
            const u32 a2 = __float_as_uint(av.z), a3 = __float_as_uint(av.w);
            const float* r0 = sC + (8*k + t4) * CSTRIDE + 16*nt + g8;
            const float* r4 = r0 + 4 * CSTRIDE;
            u32 b0 = __float_as_uint(r0[0]);
            u32 b1 = __float_as_uint(r4[0]);
            mma_tf32(D2[0], a0, a1, a2, a3, b0, b1);
            b0 = __float_as_uint(r0[8]);
            b1 = __float_as_uint(r4[8]);
            mma_tf32(D2[1], a0, a1, a2, a3, b0, b1);
        }

        // ---- epi2: head partials, reduce over rows within warp ----
        {
            const int ro = 16*m + g8;
            const float wa  = sWa2v[ro],   wb  = sWa2v[ro + 8];
            const float caa = sca[ro],     cab = sca[ro + 8];
            float p0 = wa * tanhp(D2[0][0] + caa) + wb * tanhp(D2[0][2] + cab);
            float p1 = wa * tanhp(D2[0][1] + caa) + wb * tanhp(D2[0][3] + cab);
            float p2 = wa * tanhp(D2[1][0] + caa) + wb * tanhp(D2[1][2] + cab);
            float p3 = wa * tanhp(D2[1][1] + caa) + wb * tanhp(D2[1][3] + cab);
            const unsigned m32 = 0xffffffffu;
            #pragma unroll
            for (int off = 4; off <= 16; off <<= 1) {
                p0 += __shfl_xor_sync(m32, p0, off);
                p1 += __shfl_xor_sync(m32, p1, off);
                p2 += __shfl_xor_sync(m32, p2, off);
                p3 += __shfl_xor_sync(m32, p3, off);
            }
            if (g8 == 0) {
                const int c0 = 16*nt + 2*t4;
                sPart[m][c0]     = p0;
                sPart[m][c0 + 1] = p1;
                sPart[m][c0 + 8] = p2;
                sPart[m][c0 + 9] = p3;
            }
        }
        __syncthreads();

        // ---- tail: warp 0 softmax + min-max norm ----
        if (warp == 0) {
            const int a0 = lane, a1 = lane + 32;
            const float lg0 = tanhp(sPart[0][a0] + sPart[1][a0] + sba2[0]);
            const float lg1 = tanhp(sPart[0][a1] + sPart[1][a1] + sba2[0]);

            const unsigned m32 = 0xffffffffu;
            float mx = fmaxf(lg0, lg1);
            float mn = fminf(lg0, lg1);
            #pragma unroll
            for (int off = 16; off > 0; off >>= 1) {
                mx = fmaxf(mx, __shfl_xor_sync(m32, mx, off));
                mn = fminf(mn, __shfl_xor_sync(m32, mn, off));
            }
            const float e0 = expf(lg0 - mx);
            const float e1 = expf(lg1 - mx);
            float ssum = e0 + e1;
            #pragma unroll
            for (int off = 16; off > 0; off >>= 1) ssum += __shfl_xor_sync(m32, ssum, off);
            const float invs = 1.0f / ssum;

            const float w0  = e0 * invs;
            const float w1  = e1 * invs;
            const float wmn = expf(mn - mx) * invs;
            const float wmx = invs;
            const float kk  = (1.0f + 1e-6f) / (wmx - wmn + 1e-6f);

            float* ob = out + (size_t)gp * NAc;
            float* on = ob + (size_t)BZc * NUMc * NAc;
            ob[a0] = w0;
            ob[a1] = w1;
            on[a0] = kk * (w0 - wmn);
            on[a1] = kk * (w1 - wmn);
        }
    }
}

// ---------------- launch ----------------
extern "C" void kernel_launch(void* const* d_in, const int* in_sizes, int n_in,
                              void* d_out, int out_size)
{
    const float* loc  = (const float*)d_in[0];
    const float* feat = (const float*)d_in[1];

    disarm_prep<<<1, 256>>>(
        (const float*)d_in[2],  (const float*)d_in[3],  (const float*)d_in[4],  (const float*)d_in[5],
        (const float*)d_in[6],  (const float*)d_in[7],
        (const float*)d_in[8],  (const float*)d_in[9],  (const float*)d_in[10], (const float*)d_in[11],
        (const float*)d_in[12], (const float*)d_in[13], (const float*)d_in[14], (const float*)d_in[15],
        (const float*)d_in[16], (const float*)d_in[17],
        (const float*)d_in[18], (const float*)d_in[19], (const float*)d_in[20], (const float*)d_in[21],
        (const float*)d_in[22], (const float*)d_in[23]);

    static int smem_set = 0;
    if (!smem_set) {
        cudaFuncSetAttribute(disarm_mma,
                             cudaFuncAttributeMaxDynamicSharedMemorySize, SM_TOTAL);
        smem_set = 1;
    }
    disarm_mma<<<(BZc * NUMc) / GRPS, 256, SM_TOTAL>>>(loc, feat, (float*)d_out);
}

// round 7
// speedup vs baseline: 2.6574x; 1.1542x over previous
#include <cuda_runtime.h>
#include <cstdint>

// Problem dims
#define BZc   8
#define NUMc  1024
#define NAc   64
#define FDc   128
#define GRPS  8          // (b,p) groups per CTA

typedef unsigned long long u64;
typedef unsigned int u32;

// ---------------- helpers ----------------
__device__ __forceinline__ float tanha(float x) {           // HW approx, hidden only
    float y; asm("tanh.approx.f32 %0, %1;" : "=f"(y) : "f"(x)); return y;
}
// Fast precise tanh: ex2 + rcp + 1 Newton step (~4e-7). Head/logit path.
__device__ __forceinline__ float tanhp(float x) {
    float t; asm("ex2.approx.f32 %0, %1;" : "=f"(t) : "f"(x * 2.8853900817779268f));
    float d = 1.0f + t;
    float r; asm("rcp.approx.f32 %0, %1;" : "=f"(r) : "f"(d));
    r = fmaf(fmaf(-d, r, 1.0f), r, r);
    return fmaf(-2.0f, r, 1.0f);
}
__device__ __forceinline__ float to_tf32(float x) {
    float y; asm("cvt.rna.tf32.f32 %0, %1;" : "=f"(y) : "f"(x)); return y;
}
__device__ __forceinline__ void mma_tf32(float d[4],
    u32 a0, u32 a1, u32 a2, u32 a3, u32 b0, u32 b1)
{
    asm("mma.sync.aligned.m16n8k8.row.col.f32.tf32.tf32.f32 "
        "{%0,%1,%2,%3}, {%4,%5,%6,%7}, {%8,%9}, {%0,%1,%2,%3};"
        : "+f"(d[0]), "+f"(d[1]), "+f"(d[2]), "+f"(d[3])
        : "r"(a0), "r"(a1), "r"(a2), "r"(a3), "r"(b0), "r"(b1));
}
__device__ __forceinline__ void cpa16(u32 dst, const void* src) {
    asm volatile("cp.async.cg.shared.global [%0], [%1], 16;" :: "r"(dst), "l"(src));
}
#define CP_COMMIT() asm volatile("cp.async.commit_group;")
#define CP_WAIT0()  asm volatile("cp.async.wait_group 0;")

// ---------------- folded weight storage (fragment layouts) ----------------
__device__ float4 g_WtF[4 * 16 * 32];   // A1 frags [tile][k][lane]
__device__ float4 g_M2F[2 * 10 * 32];   // M2 frags [m][k][lane]
__device__ float g_c1[64];
__device__ float g_ca[32];
__device__ float g_B1[8][4];
__device__ float g_d1[8];
__device__ float g_B2[16][8];
__device__ float g_d2[16];
__device__ float g_Wa2[32];
__device__ float g_ba2s;

// ---------------- weight folding kernel ----------------
__global__ void disarm_prep(
    const float* __restrict__ Wf1, const float* __restrict__ bf1,
    const float* __restrict__ gf1, const float* __restrict__ btf1,
    const float* __restrict__ Wf2, const float* __restrict__ bf2,
    const float* __restrict__ Ws1, const float* __restrict__ bs1,
    const float* __restrict__ gs1, const float* __restrict__ bts1,
    const float* __restrict__ Ws2, const float* __restrict__ bs2,
    const float* __restrict__ gs2, const float* __restrict__ bts2,
    const float* __restrict__ Ws3, const float* __restrict__ bs3,
    const float* __restrict__ Wa1, const float* __restrict__ ba1,
    const float* __restrict__ ga1, const float* __restrict__ bta1,
    const float* __restrict__ Wa2, const float* __restrict__ ba2)
{
    const float inv = rsqrtf(1.0f + 1e-5f);
    const int t = threadIdx.x;
    const int nt = blockDim.x;

    auto wt = [&](int r, int c) -> float {
        return to_tf32(gf1[r] * inv * Wf1[r * FDc + c]);
    };
    for (int i = t; i < 4 * 16 * 32; i += nt) {
        int tile = i >> 9, k = (i >> 5) & 15, lane = i & 31;
        int g8 = lane >> 2, t4 = lane & 3;
        int r = 16 * tile + g8, c = 8 * k + t4;
        g_WtF[i] = make_float4(wt(r, c), wt(r + 8, c), wt(r, c + 4), wt(r + 8, c + 4));
    }
    auto m2 = [&](int o, int kk) -> float {
        float acc = 0.0f;
        if (kk < 64) {
            for (int j = 0; j < 32; ++j) acc += Wa1[o*64 + 32 + j] * Wf2[j*64 + kk];
        } else {
            for (int m = 0; m < 32; ++m) acc += Wa1[o*64 + m] * Ws3[m*16 + (kk - 64)];
        }
        return to_tf32(ga1[o] * inv * acc);
    };
    for (int i = t; i < 2 * 10 * 32; i += nt) {
        int m = i / (10 * 32), k = (i / 32) % 10, lane = i & 31;
        int g8 = lane >> 2, t4 = lane & 3;
        int r = 16 * m + g8, c = 8 * k + t4;
        g_M2F[i] = make_float4(m2(r, c), m2(r + 8, c), m2(r, c + 4), m2(r + 8, c + 4));
    }
    for (int i = t; i < 64; i += nt) g_c1[i] = gf1[i]*inv*bf1[i] + btf1[i];
    if (t < 32) {
        float acc = 0.0f;
        for (int j = 0; j < 32; ++j) acc += Wa1[t*64 + 32 + j] * bf2[j];
        for (int m = 0; m < 32; ++m) acc += Wa1[t*64 + m] * bs3[m];
        g_ca[t] = ga1[t]*inv*(acc + ba1[t]) + bta1[t];
    }
    if (t < 8) {
        for (int i = 0; i < 3; ++i) g_B1[t][i] = gs1[t]*inv*Ws1[t*3 + i];
        g_B1[t][3] = 0.0f;
        g_d1[t] = gs1[t]*inv*bs1[t] + bts1[t];
    }
    if (t < 16) {
        for (int i = 0; i < 8; ++i) g_B2[t][i] = gs2[t]*inv*Ws2[t*8 + i];
        g_d2[t] = gs2[t]*inv*bs2[t] + bts2[t];
    }
    if (t < 32) g_Wa2[t] = Wa2[t];
    if (t == 0) g_ba2s = ba2[0];
}

// ---------------- smem layout (bytes) ----------------
#define XSTRIDE  72                 // floats/row; LDS.128 frag loads conflict-free
#define XBUF     (FDc * XSTRIDE * 4)        // 36864 per buffer
#define CSTRIDE  72
#define SM_X     0                          // 2 buffers: 73728
#define SM_C     (2 * XBUF)                 // 80*72*4 = 23040
#define SM_M2F   (SM_C + 23040)             // 640 float4 = 10240
#define SM_PART  (SM_M2F + 10240)           // 2 bufs * 2 * 64 * 4 = 1024
#define SM_C1    (SM_PART + 1024)           // 256
#define SM_CA    (SM_C1 + 256)              // 128
#define SM_WA2   (SM_CA + 128)              // 128
#define SM_B1    (SM_WA2 + 128)             // 128
#define SM_D1    (SM_B1 + 128)              // 32
#define SM_B2    (SM_D1 + 32)               // 512
#define SM_D2    (SM_B2 + 512)              // 64
#define SM_BA2   (SM_D2 + 64)               // 16
#define SM_TOTAL (SM_BA2 + 16)

// ---------------- main fused kernel ----------------
// Anchor-column permutation: mma1 column (tile n, col c) carries logical
// anchor 32*wN + 4*c + n; mma2 column (tile n2, col c) carries logical anchor
// 16*nt + 2*c + n2. sC/outputs stay in natural anchor layout; the remap makes
// every B-fragment load a vector LDS and every epilogue store a vector STS.
__global__ void __launch_bounds__(256, 2) disarm_mma(
    const float* __restrict__ loc, const float* __restrict__ feat,
    float* __restrict__ out)
{
    extern __shared__ char smem[];
    float* sX    = (float*)(smem + SM_X);
    float* sC    = (float*)(smem + SM_C);
    float4* sM2F = (float4*)(smem + SM_M2F);
    float (*sPart)[2][64] = (float (*)[2][64])(smem + SM_PART);  // [buf][m][a]
    float* sc1   = (float*)(smem + SM_C1);
    float* sca   = (float*)(smem + SM_CA);
    float* sWa2v = (float*)(smem + SM_WA2);
    float (*sB1)[4] = (float (*)[4])(smem + SM_B1);
    float* sd1   = (float*)(smem + SM_D1);
    float (*sB2)[8] = (float (*)[8])(smem + SM_B2);
    float* sd2   = (float*)(smem + SM_D2);
    float* sba2  = (float*)(smem + SM_BA2);

    u32 sbase;
    asm("{.reg .u64 t; cvta.to.shared.u64 t, %1; cvt.u32.u64 %0, t;}"
        : "=r"(sbase) : "l"(smem));

    const int tid  = threadIdx.x;
    const int warp = tid >> 5;
    const int lane = tid & 31;
    const int g8   = lane >> 2;
    const int t4   = lane & 3;
    const int wM   = warp >> 1;   // mma1 row tile
    const int wN   = warp & 1;    // mma1 anchor half
    const int m    = warp & 1;    // mma2 row half
    const int nt   = warp >> 1;   // mma2 anchor 16-col tile

    const size_t cs = (size_t)NUMc * NAc;
    const int gp0 = blockIdx.x * GRPS;

    // ---- issue cp.async for group 0's X tile ----
    {
        const int b = gp0 >> 10, p = gp0 & 1023;
        const float* fbase = feat + (size_t)b * FDc * cs + (size_t)p * NAc;
        for (int i = tid; i < FDc * 16; i += 256) {
            int r = i >> 4, c16 = i & 15;
            cpa16(sbase + SM_X + r * (XSTRIDE*4) + c16 * 16,
                  fbase + (size_t)r * cs + c16 * 4);
        }
        CP_COMMIT();
    }

    // ---- persistent A1 fragments (coalesced LDG.128, once per CTA) ----
    u32 A[64];
    {
        const float4* aw = g_WtF + (size_t)wM * 16 * 32 + lane;
        #pragma unroll
        for (int k = 0; k < 16; ++k) {
            float4 v = __ldg(aw + k * 32);
            A[4*k+0] = __float_as_uint(v.x);
            A[4*k+1] = __float_as_uint(v.y);
            A[4*k+2] = __float_as_uint(v.z);
            A[4*k+3] = __float_as_uint(v.w);
        }
    }

    // ---- stage M2 fragments + small weights (once per CTA) ----
    for (int i = tid; i < 640; i += 256) sM2F[i] = g_M2F[i];
    if (tid < 64) sc1[tid] = g_c1[tid];
    if (tid < 32) { sca[tid] = g_ca[tid]; sWa2v[tid] = g_Wa2[tid]; }
    if (tid < 32) sB1[tid>>2][tid&3] = g_B1[tid>>2][tid&3];
    if (tid < 8)  sd1[tid] = g_d1[tid];
    if (tid >= 128 && tid < 256) sB2[(tid-128)>>3][(tid-128)&7] = g_B2[(tid-128)>>3][(tid-128)&7];
    if (tid < 16) sd2[tid] = g_d2[tid];
    if (tid == 0) sba2[0] = g_ba2s;

    const int sa   = tid & 63;       // spatial anchor
    const int sos  = tid >> 6;       // spatial output slice (4 outputs)

    CP_WAIT0();
    __syncthreads();                 // X[0] + staged weights visible

    #pragma unroll 1
    for (int g = 0; g < GRPS; ++g) {
        const int gp = gp0 + g;
        const int b  = gp >> 10;
        const int p  = gp & 1023;
        float* xb = sX + (g & 1) * (FDc * XSTRIDE);

        // prefetch X for group g+1 into the other buffer
        if (g + 1 < GRPS) {
            const int gp1 = gp + 1;
            const int b1 = gp1 >> 10, p1 = gp1 & 1023;
            const float* fb1 = feat + (size_t)b1 * FDc * cs + (size_t)p1 * NAc;
            u32 dst = sbase + SM_X + ((g + 1) & 1) * XBUF;
            for (int i = tid; i < FDc * 16; i += 256) {
                int r = i >> 4, c16 = i & 15;
                cpa16(dst + r * (XSTRIDE*4) + c16 * 16,
                      fb1 + (size_t)r * cs + c16 * 4);
            }
            CP_COMMIT();
        }

        // early loc load (latency hides under mma1)
        const float* lp = loc + (((size_t)(b*NUMc + p))*NAc + sa) * 3;
        const float l0 = __ldg(lp), l1 = __ldg(lp + 1), l2 = __ldg(lp + 2);

        // ---- mma1: H tile = W1 @ X (64 mma/warp, vector B loads) ----
        // thread loads anchors [32wN + 4g8 .. +3] = tiles n=0..3 at frag col g8
        float D[4][4];
        #pragma unroll
        for (int n = 0; n < 4; ++n) { D[n][0]=0.f; D[n][1]=0.f; D[n][2]=0.f; D[n][3]=0.f; }
        #pragma unroll
        for (int k = 0; k < 16; ++k) {
            const float* rr = xb + (8*k + t4) * XSTRIDE + 32*wN + 4*g8;
            const float4 v0 = *(const float4*)rr;
            const float4 v1 = *(const float4*)(rr + 4*XSTRIDE);
            mma_tf32(D[0], A[4*k], A[4*k+1], A[4*k+2], A[4*k+3],
                     __float_as_uint(v0.x), __float_as_uint(v1.x));
            mma_tf32(D[1], A[4*k], A[4*k+1], A[4*k+2], A[4*k+3],
                     __float_as_uint(v0.y), __float_as_uint(v1.y));
            mma_tf32(D[2], A[4*k], A[4*k+1], A[4*k+2], A[4*k+3],
                     __float_as_uint(v0.z), __float_as_uint(v1.z));
            mma_tf32(D[3], A[4*k], A[4*k+1], A[4*k+2], A[4*k+3],
                     __float_as_uint(v0.w), __float_as_uint(v1.w));
        }

        // ---- spatial branch -> C rows 64..79 (natural anchor layout) ----
        {
            float s1v[8];
            #pragma unroll
            for (int j = 0; j < 8; ++j)
                s1v[j] = tanha(sB1[j][0]*l0 + sB1[j][1]*l1 + sB1[j][2]*l2 + sd1[j]);
            #pragma unroll
            for (int jj = 0; jj < 4; ++jj) {
                const int o = 4*sos + jj;
                float acc = sd2[o];
                #pragma unroll
                for (int i = 0; i < 8; ++i) acc += sB2[o][i] * s1v[i];
                sC[(64 + o) * CSTRIDE + sa] = to_tf32(tanha(acc));
            }
        }

        // ---- epi1: tanh(H + c1) -> C rows 0..63 (vector stores) ----
        // D[n] frag col 2t4+s = logical anchor 32wN + 8t4 + 4s + n
        {
            const int ro = 16*wM + g8;
            const float c1a = sc1[ro];
            const float c1b = sc1[ro + 8];
            float* cr0 = sC + ro * CSTRIDE + 32*wN + 8*t4;
            float* cr8 = cr0 + 8 * CSTRIDE;
            float4 v;
            v.x = to_tf32(tanha(D[0][0] + c1a)); v.y = to_tf32(tanha(D[1][0] + c1a));
            v.z = to_tf32(tanha(D[2][0] + c1a)); v.w = to_tf32(tanha(D[3][0] + c1a));
            *(float4*)cr0 = v;
            v.x = to_tf32(tanha(D[0][1] + c1a)); v.y = to_tf32(tanha(D[1][1] + c1a));
            v.z = to_tf32(tanha(D[2][1] + c1a)); v.w = to_tf32(tanha(D[3][1] + c1a));
            *(float4*)(cr0 + 4) = v;
            v.x = to_tf32(tanha(D[0][2] + c1b)); v.y = to_tf32(tanha(D[1][2] + c1b));
            v.z = to_tf32(tanha(D[2][2] + c1b)); v.w = to_tf32(tanha(D[3][2] + c1b));
            *(float4*)cr8 = v;
            v.x = to_tf32(tanha(D[0][3] + c1b)); v.y = to_tf32(tanha(D[1][3] + c1b));
            v.z = to_tf32(tanha(D[2][3] + c1b)); v.w = to_tf32(tanha(D[3][3] + c1b));
            *(float4*)(cr8 + 4) = v;
        }
        __syncthreads();            // sC ready; X[g] reads done

        // ---- mma2: A2[32x64] = M2 @ C (20 mma/warp, float2 B loads) ----
        // thread loads anchors 16nt + 2g8, +1 = tiles n2=0,1 at frag col g8
        float D2[2][4];
        D2[0][0]=0.f; D2[0][1]=0.f; D2[0][2]=0.f; D2[0][3]=0.f;
        D2[1][0]=0.f; D2[1][1]=0.f; D2[1][2]=0.f; D2[1][3]=0.f;
        #pragma unroll
        for (int k = 0; k < 10; ++k) {
            float4 av = sM2F[(m * 10 + k) * 32 + lane];
            const u32 a0 = __float_as_uint(av.x), a1 = __float_as_uint(av.y);
            const u32 a2 = __float_as_uint(av.z), a3 = __float_as_uint(av.w);
            const float* rr = sC + (8*k + t4) * CSTRIDE + 16*nt + 2*g8;
            const float2 v0 = *(const float2*)rr;
            const float2 v1 = *(const float2*)(rr + 4*CSTRIDE);
            mma_tf32(D2[0], a0, a1, a2, a3, __float_as_uint(v0.x), __float_as_uint(v1.x));
            mma_tf32(D2[1], a0, a1, a2, a3, __float_as_uint(v0.y), __float_as_uint(v1.y));
        }

        // ---- epi2: head partials; D2[n2] frag col 2t4+s = anchor 16nt+4t4+2s+n2
        {
            const int ro = 16*m + g8;
            const float wa  = sWa2v[ro],   wb  = sWa2v[ro + 8];
            const float caa = sca[ro],     cab = sca[ro + 8];
            float p0 = wa * tanhp(D2[0][0] + caa) + wb * tanhp(D2[0][2] + cab); // +0
            float p2 = wa * tanhp(D2[1][0] + caa) + wb * tanhp(D2[1][2] + cab); // +1
            float p1 = wa * tanhp(D2[0][1] + caa) + wb * tanhp(D2[0][3] + cab); // +2
            float p3 = wa * tanhp(D2[1][1] + caa) + wb * tanhp(D2[1][3] + cab); // +3
            const unsigned m32 = 0xffffffffu;
            #pragma unroll
            for (int off = 4; off <= 16; off <<= 1) {
                p0 += __shfl_xor_sync(m32, p0, off);
                p1 += __shfl_xor_sync(m32, p1, off);
                p2 += __shfl_xor_sync(m32, p2, off);
                p3 += __shfl_xor_sync(m32, p3, off);
            }
            if (g8 == 0) {
                float4 v; v.x = p0; v.y = p2; v.z = p1; v.w = p3;
                *(float4*)&sPart[g & 1][m][16*nt + 4*t4] = v;
            }
        }

        CP_WAIT0();                 // X[g+1] copies landed (own thread)
        __syncthreads();            // sPart + X[g+1] visible; sC reads done

        // ---- tail: warp 0 softmax + min-max norm (overlaps next mma1) ----
        if (warp == 0) {
            const int a0 = lane, a1 = lane + 32;
            const float* pb0 = sPart[g & 1][0];
            const float* pb1 = sPart[g & 1][1];
            const float lg0 = tanhp(pb0[a0] + pb1[a0] + sba2[0]);
            const float lg1 = tanhp(pb0[a1] + pb1[a1] + sba2[0]);

            const unsigned m32 = 0xffffffffu;
            float mx = fmaxf(lg0, lg1);
            float mn = fminf(lg0, lg1);
            #pragma unroll
            for (int off = 16; off > 0; off >>= 1) {
                mx = fmaxf(mx, __shfl_xor_sync(m32, mx, off));
                mn = fminf(mn, __shfl_xor_sync(m32, mn, off));
            }
            const float e0 = expf(lg0 - mx);
            const float e1 = expf(lg1 - mx);
            float ssum = e0 + e1;
            #pragma unroll
            for (int off = 16; off > 0; off >>= 1) ssum += __shfl_xor_sync(m32, ssum, off);
            const float invs = 1.0f / ssum;

            const float w0  = e0 * invs;
            const float w1  = e1 * invs;
            const float wmn = expf(mn - mx) * invs;
            const float wmx = invs;
            const float kk  = (1.0f + 1e-6f) / (wmx - wmn + 1e-6f);

            float* ob = out + (size_t)gp * NAc;
            float* on = ob + (size_t)BZc * NUMc * NAc;
            ob[a0] = w0;
            ob[a1] = w1;
            on[a0] = kk * (w0 - wmn);
            on[a1] = kk * (w1 - wmn);
        }
    }
}

// ---------------- launch ----------------
extern "C" void kernel_launch(void* const* d_in, const int* in_sizes, int n_in,
                              void* d_out, int out_size)
{
    const float* loc  = (const float*)d_in[0];
    const float* feat = (const float*)d_in[1];

    disarm_prep<<<1, 256>>>(
        (const float*)d_in[2],  (const float*)d_in[3],  (const float*)d_in[4],  (const float*)d_in[5],
        (const float*)d_in[6],  (const float*)d_in[7],
        (const float*)d_in[8],  (const float*)d_in[9],  (const float*)d_in[10], (const float*)d_in[11],
        (const float*)d_in[12], (const float*)d_in[13], (const float*)d_in[14], (const float*)d_in[15],
        (const float*)d_in[16], (const float*)d_in[17],
        (const float*)d_in[18], (const float*)d_in[19], (const float*)d_in[20], (const float*)d_in[21],
        (const float*)d_in[22], (const float*)d_in[23]);

    static int smem_set = 0;
    if (!smem_set) {
        cudaFuncSetAttribute(disarm_mma,
                             cudaFuncAttributeMaxDynamicSharedMemorySize, SM_TOTAL);
        smem_set = 1;
    }
    disarm_mma<<<(BZc * NUMc) / GRPS, 256, SM_TOTAL>>>(loc, feat, (float*)d_out);
}

// round 8
// speedup vs baseline: 3.1589x; 1.1887x over previous
#include <cuda_runtime.h>
#include <cuda_fp16.h>
#include <cstdint>

// Problem dims
#define BZc   8
#define NUMc  1024
#define NAc   64
#define FDc   128
#define GRPS  8          // (b,p) groups per CTA

typedef unsigned int u32;

// ---------------- helpers ----------------
__device__ __forceinline__ float tanha(float x) {           // HW approx, hidden only
    float y; asm("tanh.approx.f32 %0, %1;" : "=f"(y) : "f"(x)); return y;
}
// Fast precise tanh: ex2 + rcp + 1 Newton step (~4e-7). Head/logit path.
__device__ __forceinline__ float tanhp(float x) {
    float t; asm("ex2.approx.f32 %0, %1;" : "=f"(t) : "f"(x * 2.8853900817779268f));
    float d = 1.0f + t;
    float r; asm("rcp.approx.f32 %0, %1;" : "=f"(r) : "f"(d));
    r = fmaf(fmaf(-d, r, 1.0f), r, r);
    return fmaf(-2.0f, r, 1.0f);
}
__device__ __forceinline__ u32 pkh2(float a, float b) {
    __half2 h = __floats2half2_rn(a, b);
    return *(u32*)&h;
}
__device__ __forceinline__ void mma_f16(float d[4],
    u32 a0, u32 a1, u32 a2, u32 a3, u32 b0, u32 b1)
{
    asm("mma.sync.aligned.m16n8k16.row.col.f32.f16.f16.f32 "
        "{%0,%1,%2,%3}, {%4,%5,%6,%7}, {%8,%9}, {%0,%1,%2,%3};"
        : "+f"(d[0]), "+f"(d[1]), "+f"(d[2]), "+f"(d[3])
        : "r"(a0), "r"(a1), "r"(a2), "r"(a3), "r"(b0), "r"(b1));
}

// ---------------- folded weight storage (fp16 fragment layouts) ----------------
__device__ uint4 g_WhF[4 * 8 * 32];   // A1 frags [tile(4)][kk(8)][lane(32)]
__device__ uint4 g_M2hF[2 * 5 * 32];  // M2 frags [m(2)][kk2(5)][lane(32)]
__device__ float g_c1[64];
__device__ float g_ca[32];
__device__ float g_B1[8][4];
__device__ float g_d1[8];
__device__ float g_B2[16][8];
__device__ float g_d2[16];
__device__ float g_Wa2[32];
__device__ float g_ba2s;

// ---------------- weight folding kernel ----------------
__global__ void disarm_prep(
    const float* __restrict__ Wf1, const float* __restrict__ bf1,
    const float* __restrict__ gf1, const float* __restrict__ btf1,
    const float* __restrict__ Wf2, const float* __restrict__ bf2,
    const float* __restrict__ Ws1, const float* __restrict__ bs1,
    const float* __restrict__ gs1, const float* __restrict__ bts1,
    const float* __restrict__ Ws2, const float* __restrict__ bs2,
    const float* __restrict__ gs2, const float* __restrict__ bts2,
    const float* __restrict__ Ws3, const float* __restrict__ bs3,
    const float* __restrict__ Wa1, const float* __restrict__ ba1,
    const float* __restrict__ ga1, const float* __restrict__ bta1,
    const float* __restrict__ Wa2, const float* __restrict__ ba2)
{
    const float inv = rsqrtf(1.0f + 1e-5f);
    const int t = threadIdx.x;
    const int nt = blockDim.x;

    auto wt = [&](int r, int c) -> float {
        return gf1[r] * inv * Wf1[r * FDc + c];
    };
    // A1 fp16 fragments: m16n8k16 A layout (row-major).
    for (int i = t; i < 4 * 8 * 32; i += nt) {
        int tile = i >> 8, kk = (i >> 5) & 7, lane = i & 31;
        int g8 = lane >> 2, t4 = lane & 3;
        int r = 16 * tile + g8, c = 16 * kk + 2 * t4;
        uint4 v;
        v.x = pkh2(wt(r,     c), wt(r,     c + 1));
        v.y = pkh2(wt(r + 8, c), wt(r + 8, c + 1));
        v.z = pkh2(wt(r,     c + 8), wt(r,     c + 9));
        v.w = pkh2(wt(r + 8, c + 8), wt(r + 8, c + 9));
        g_WhF[i] = v;
    }
    // folded agg value M2[o][kk]: kk<64 feature-hidden, kk>=64 spatial
    auto m2 = [&](int o, int kk) -> float {
        float acc = 0.0f;
        if (kk < 64) {
            for (int j = 0; j < 32; ++j) acc += Wa1[o*64 + 32 + j] * Wf2[j*64 + kk];
        } else {
            for (int mq = 0; mq < 32; ++mq) acc += Wa1[o*64 + mq] * Ws3[mq*16 + (kk - 64)];
        }
        return ga1[o] * inv * acc;
    };
    // k-pair unit map: pair p<32 -> hidden rows (16(p>>3)+(p&7)) and +8;
    //                  p>=32 -> spatial units 2(p-32), +1 (cols 64+..)
    auto U = [&](int p, int e) -> int {
        if (p < 32) return 16 * (p >> 3) + (p & 7) + 8 * e;
        return 64 + 2 * (p - 32) + e;
    };
    for (int i = t; i < 2 * 5 * 32; i += nt) {
        int m = i / (5 * 32), kk2 = (i / 32) % 5, lane = i & 31;
        int g8 = lane >> 2, t4 = lane & 3;
        int r = 16 * m + g8;
        int p = 8 * kk2 + t4;
        uint4 v;
        v.x = pkh2(m2(r,     U(p, 0)),     m2(r,     U(p, 1)));
        v.y = pkh2(m2(r + 8, U(p, 0)),     m2(r + 8, U(p, 1)));
        v.z = pkh2(m2(r,     U(p + 4, 0)), m2(r,     U(p + 4, 1)));
        v.w = pkh2(m2(r + 8, U(p + 4, 0)), m2(r + 8, U(p + 4, 1)));
        g_M2hF[i] = v;
    }
    for (int i = t; i < 64; i += nt) g_c1[i] = gf1[i]*inv*bf1[i] + btf1[i];
    if (t < 32) {
        float acc = 0.0f;
        for (int j = 0; j < 32; ++j) acc += Wa1[t*64 + 32 + j] * bf2[j];
        for (int mq = 0; mq < 32; ++mq) acc += Wa1[t*64 + mq] * bs3[mq];
        g_ca[t] = ga1[t]*inv*(acc + ba1[t]) + bta1[t];
    }
    if (t < 8) {
        for (int i = 0; i < 3; ++i) g_B1[t][i] = gs1[t]*inv*Ws1[t*3 + i];
        g_B1[t][3] = 0.0f;
        g_d1[t] = gs1[t]*inv*bs1[t] + bts1[t];
    }
    if (t < 16) {
        for (int i = 0; i < 8; ++i) g_B2[t][i] = gs2[t]*inv*Ws2[t*8 + i];
        g_d2[t] = gs2[t]*inv*bs2[t] + bts2[t];
    }
    if (t < 32) g_Wa2[t] = Wa2[t];
    if (t == 0) g_ba2s = ba2[0];
}

// ---------------- smem layout (bytes) ----------------
// X half tile: rows = channel-pair cp (64), cols = anchor half2 (64), stride 72 u32.
// C half tile: rows = k-pair (40), cols = anchor half2 (64), stride 72 u32.
#define XHS      72                         // u32 per cp row
#define XHBUF    (64 * XHS * 4)             // 18432 B
#define CHS      72
#define SM_XH    0                          // 2 buffers: 36864
#define SM_CH    (2 * XHBUF)                // 40*72*4 = 11520
#define SM_PART  (SM_CH + 11520)            // 2 bufs * 2 * 64 * 4 = 1024
#define SM_C1    (SM_PART + 1024)           // 256
#define SM_CA    (SM_C1 + 256)              // 128
#define SM_WA2   (SM_CA + 128)              // 128
#define SM_B1    (SM_WA2 + 128)             // 128
#define SM_D1    (SM_B1 + 128)              // 32
#define SM_B2    (SM_D1 + 32)               // 512
#define SM_D2    (SM_B2 + 512)              // 64
#define SM_BA2   (SM_D2 + 64)               // 16
#define SM_TOTAL (SM_BA2 + 16)

// ---------------- main fused kernel ----------------
// fp16 mma datapath. mma1: H[64x64]=W1@X, warp (wM,wN) = 16 rows x 32 anchors,
// anchor perm: tile n col c -> anchor 32wN+4c+n (vector LDS.128 B loads).
// C stored as half2 k-pairs (mma1 rows g8/g8+8 paired; M2 columns permuted in prep).
// mma2: A2[32x64]=M2@C, M2 frags persistent in registers (20 regs fp16).
// X staged by LDG->cvt->STS half2, double-buffered, prefetched one group ahead.
__global__ void __launch_bounds__(256, 2) disarm_mma(
    const float* __restrict__ loc, const float* __restrict__ feat,
    float* __restrict__ out)
{
    extern __shared__ char smem[];
    u32* sXH = (u32*)(smem + SM_XH);
    u32* sCH = (u32*)(smem + SM_CH);
    float (*sPart)[2][64] = (float (*)[2][64])(smem + SM_PART);  // [buf][m][a]
    float* sc1   = (float*)(smem + SM_C1);
    float* sca   = (float*)(smem + SM_CA);
    float* sWa2v = (float*)(smem + SM_WA2);
    float (*sB1)[4] = (float (*)[4])(smem + SM_B1);
    float* sd1   = (float*)(smem + SM_D1);
    float (*sB2)[8] = (float (*)[8])(smem + SM_B2);
    float* sd2   = (float*)(smem + SM_D2);
    float* sba2  = (float*)(smem + SM_BA2);

    const int tid  = threadIdx.x;
    const int warp = tid >> 5;
    const int lane = tid & 31;
    const int g8   = lane >> 2;
    const int t4   = lane & 3;
    const int wM   = warp >> 1;   // mma1 row tile (0..3)
    const int wN   = warp & 1;    // mma1 anchor half (0..1)
    const int m    = warp & 1;    // mma2 row half
    const int nt   = warp >> 1;   // mma2 anchor 16-col tile

    const size_t cs = (size_t)NUMc * NAc;
    const int gp0 = blockIdx.x * GRPS;

    // ---- persistent A1 fragments (8 coalesced LDG.128) ----
    u32 A[32];
    {
        const uint4* aw = g_WhF + (size_t)wM * 8 * 32 + lane;
        #pragma unroll
        for (int kk = 0; kk < 8; ++kk) {
            uint4 v = __ldg(aw + kk * 32);
            A[4*kk+0] = v.x; A[4*kk+1] = v.y; A[4*kk+2] = v.z; A[4*kk+3] = v.w;
        }
    }
    // ---- persistent M2 fragments (5 coalesced LDG.128) ----
    u32 M[20];
    {
        const uint4* mw = g_M2hF + (size_t)m * 5 * 32 + lane;
        #pragma unroll
        for (int kk2 = 0; kk2 < 5; ++kk2) {
            uint4 v = __ldg(mw + kk2 * 32);
            M[4*kk2+0] = v.x; M[4*kk2+1] = v.y; M[4*kk2+2] = v.z; M[4*kk2+3] = v.w;
        }
    }

    // ---- stage small weights ----
    if (tid < 64) sc1[tid] = g_c1[tid];
    if (tid < 32) { sca[tid] = g_ca[tid]; sWa2v[tid] = g_Wa2[tid]; }
    if (tid < 32) sB1[tid>>2][tid&3] = g_B1[tid>>2][tid&3];
    if (tid < 8)  sd1[tid] = g_d1[tid];
    if (tid >= 128 && tid < 256) sB2[(tid-128)>>3][(tid-128)&7] = g_B2[(tid-128)>>3][(tid-128)&7];
    if (tid < 16) sd2[tid] = g_d2[tid];
    if (tid == 0) sba2[0] = g_ba2s;

    // per-thread convert indices: 4 iters of (cp, anchor-block)
    int cpi[4], abi[4];
    #pragma unroll
    for (int it = 0; it < 4; ++it) {
        int i = tid + 256 * it;
        cpi[it] = i >> 4;
        abi[it] = i & 15;
    }

    // ---- prologue: fill X half tile for group 0 ----
    {
        const int b = gp0 >> 10, p = gp0 & 1023;
        const float* fb = feat + (size_t)b * FDc * cs + (size_t)p * NAc;
        #pragma unroll
        for (int it = 0; it < 4; ++it) {
            const int cp = cpi[it], ab = abi[it];
            float4 xa = __ldg((const float4*)(fb + (size_t)(2*cp  ) * cs) + ab);
            float4 xc = __ldg((const float4*)(fb + (size_t)(2*cp+1) * cs) + ab);
            uint4 w;
            w.x = pkh2(xa.x, xc.x); w.y = pkh2(xa.y, xc.y);
            w.z = pkh2(xa.z, xc.z); w.w = pkh2(xa.w, xc.w);
            *(uint4*)(sXH + cp * XHS + 4 * ab) = w;
        }
    }
    __syncthreads();

    const int sa  = tid & 63;       // spatial anchor
    const int sos = tid >> 6;       // spatial output slice (4 outputs)

    #pragma unroll 1
    for (int g = 0; g < GRPS; ++g) {
        const int gp = gp0 + g;
        const int b  = gp >> 10;
        const int p  = gp & 1023;
        u32* xb = sXH + (g & 1) * (64 * XHS);

        // ---- prefetch group g+1's X into registers (latency hides under mma) ----
        float4 q0a, q0b, q1a, q1b, q2a, q2b, q3a, q3b;
        if (g + 1 < GRPS) {
            const int gp1 = gp + 1;
            const int b1 = gp1 >> 10, p1 = gp1 & 1023;
            const float* fb1 = feat + (size_t)b1 * FDc * cs + (size_t)p1 * NAc;
            q0a = __ldg((const float4*)(fb1 + (size_t)(2*cpi[0]  ) * cs) + abi[0]);
            q0b = __ldg((const float4*)(fb1 + (size_t)(2*cpi[0]+1) * cs) + abi[0]);
            q1a = __ldg((const float4*)(fb1 + (size_t)(2*cpi[1]  ) * cs) + abi[1]);
            q1b = __ldg((const float4*)(fb1 + (size_t)(2*cpi[1]+1) * cs) + abi[1]);
            q2a = __ldg((const float4*)(fb1 + (size_t)(2*cpi[2]  ) * cs) + abi[2]);
            q2b = __ldg((const float4*)(fb1 + (size_t)(2*cpi[2]+1) * cs) + abi[2]);
            q3a = __ldg((const float4*)(fb1 + (size_t)(2*cpi[3]  ) * cs) + abi[3]);
            q3b = __ldg((const float4*)(fb1 + (size_t)(2*cpi[3]+1) * cs) + abi[3]);
        }

        // early loc load
        const float* lp = loc + (((size_t)(b*NUMc + p))*NAc + sa) * 3;
        const float l0 = __ldg(lp), l1 = __ldg(lp + 1), l2 = __ldg(lp + 2);

        // ---- mma1: 32 fp16 mma/warp, 2 LDS.128 per kstep ----
        float D[4][4];
        #pragma unroll
        for (int n = 0; n < 4; ++n) { D[n][0]=0.f; D[n][1]=0.f; D[n][2]=0.f; D[n][3]=0.f; }
        #pragma unroll
        for (int kk = 0; kk < 8; ++kk) {
            const uint4 v0 = *(const uint4*)(xb + (8*kk + t4    ) * XHS + 32*wN + 4*g8);
            const uint4 v1 = *(const uint4*)(xb + (8*kk + t4 + 4) * XHS + 32*wN + 4*g8);
            mma_f16(D[0], A[4*kk], A[4*kk+1], A[4*kk+2], A[4*kk+3], v0.x, v1.x);
            mma_f16(D[1], A[4*kk], A[4*kk+1], A[4*kk+2], A[4*kk+3], v0.y, v1.y);
            mma_f16(D[2], A[4*kk], A[4*kk+1], A[4*kk+2], A[4*kk+3], v0.z, v1.z);
            mma_f16(D[3], A[4*kk], A[4*kk+1], A[4*kk+2], A[4*kk+3], v0.w, v1.w);
        }

        // ---- spatial branch -> C k-pairs 32..39 ----
        {
            float s1v[8];
            #pragma unroll
            for (int j = 0; j < 8; ++j)
                s1v[j] = tanha(sB1[j][0]*l0 + sB1[j][1]*l1 + sB1[j][2]*l2 + sd1[j]);
            float t0, t1, t2, t3;
            {
                float acc0 = sd2[4*sos+0], acc1 = sd2[4*sos+1];
                float acc2 = sd2[4*sos+2], acc3 = sd2[4*sos+3];
                #pragma unroll
                for (int i = 0; i < 8; ++i) {
                    acc0 += sB2[4*sos+0][i] * s1v[i];
                    acc1 += sB2[4*sos+1][i] * s1v[i];
                    acc2 += sB2[4*sos+2][i] * s1v[i];
                    acc3 += sB2[4*sos+3][i] * s1v[i];
                }
                t0 = tanha(acc0); t1 = tanha(acc1); t2 = tanha(acc2); t3 = tanha(acc3);
            }
            sCH[(32 + 2*sos) * CHS + sa] = pkh2(t0, t1);
            sCH[(33 + 2*sos) * CHS + sa] = pkh2(t2, t3);
        }

        // ---- epi1: tanh(H + c1) -> C k-pairs 0..31 (2 STS.128) ----
        // D[n] col 2t4+s -> anchor 32wN + 8t4 + 4s + n; pair pp = 8wM+g8 = (rows g8, g8+8)
        {
            const int pp = 8*wM + g8;
            const float c1a = sc1[16*wM + g8];
            const float c1b = sc1[16*wM + g8 + 8];
            u32* cw = sCH + pp * CHS + 32*wN + 8*t4;
            uint4 w;
            w.x = pkh2(tanha(D[0][0] + c1a), tanha(D[0][2] + c1b));
            w.y = pkh2(tanha(D[1][0] + c1a), tanha(D[1][2] + c1b));
            w.z = pkh2(tanha(D[2][0] + c1a), tanha(D[2][2] + c1b));
            w.w = pkh2(tanha(D[3][0] + c1a), tanha(D[3][2] + c1b));
            *(uint4*)cw = w;
            w.x = pkh2(tanha(D[0][1] + c1a), tanha(D[0][3] + c1b));
            w.y = pkh2(tanha(D[1][1] + c1a), tanha(D[1][3] + c1b));
            w.z = pkh2(tanha(D[2][1] + c1a), tanha(D[2][3] + c1b));
            w.w = pkh2(tanha(D[3][1] + c1a), tanha(D[3][3] + c1b));
            *(uint4*)(cw + 4) = w;
        }
        __syncthreads();            // sC ready; xb reads done

        // ---- mma2: 10 fp16 mma/warp, M2 frags in registers ----
        float D2[2][4];
        D2[0][0]=0.f; D2[0][1]=0.f; D2[0][2]=0.f; D2[0][3]=0.f;
        D2[1][0]=0.f; D2[1][1]=0.f; D2[1][2]=0.f; D2[1][3]=0.f;
        #pragma unroll
        for (int kk2 = 0; kk2 < 5; ++kk2) {
            const uint2 w0 = *(const uint2*)(sCH + (8*kk2 + t4    ) * CHS + 16*nt + 2*g8);
            const uint2 w1 = *(const uint2*)(sCH + (8*kk2 + t4 + 4) * CHS + 16*nt + 2*g8);
            mma_f16(D2[0], M[4*kk2], M[4*kk2+1], M[4*kk2+2], M[4*kk2+3], w0.x, w1.x);
            mma_f16(D2[1], M[4*kk2], M[4*kk2+1], M[4*kk2+2], M[4*kk2+3], w0.y, w1.y);
        }

        // ---- epi2: head partials; D2[n2] col 2t4+s -> anchor 16nt+4t4+2s+n2 ----
        {
            const int ro = 16*m + g8;
            const float wa  = sWa2v[ro],   wb  = sWa2v[ro + 8];
            const float caa = sca[ro],     cab = sca[ro + 8];
            float p0 = wa * tanhp(D2[0][0] + caa) + wb * tanhp(D2[0][2] + cab); // +0
            float p2 = wa * tanhp(D2[1][0] + caa) + wb * tanhp(D2[1][2] + cab); // +1
            float p1 = wa * tanhp(D2[0][1] + caa) + wb * tanhp(D2[0][3] + cab); // +2
            float p3 = wa * tanhp(D2[1][1] + caa) + wb * tanhp(D2[1][3] + cab); // +3
            const unsigned m32 = 0xffffffffu;
            #pragma unroll
            for (int off = 4; off <= 16; off <<= 1) {
                p0 += __shfl_xor_sync(m32, p0, off);
                p1 += __shfl_xor_sync(m32, p1, off);
                p2 += __shfl_xor_sync(m32, p2, off);
                p3 += __shfl_xor_sync(m32, p3, off);
            }
            if (g8 == 0) {
                float4 v; v.x = p0; v.y = p2; v.z = p1; v.w = p3;
                *(float4*)&sPart[g & 1][m][16*nt + 4*t4] = v;
            }
        }

        // ---- convert + store X[g+1] (LDG latency fully elapsed by now) ----
        if (g + 1 < GRPS) {
            u32* xd = sXH + ((g + 1) & 1) * (64 * XHS);
            uint4 w;
            w.x = pkh2(q0a.x, q0b.x); w.y = pkh2(q0a.y, q0b.y);
            w.z = pkh2(q0a.z, q0b.z); w.w = pkh2(q0a.w, q0b.w);
            *(uint4*)(xd + cpi[0] * XHS + 4 * abi[0]) = w;
            w.x = pkh2(q1a.x, q1b.x); w.y = pkh2(q1a.y, q1b.y);
            w.z = pkh2(q1a.z, q1b.z); w.w = pkh2(q1a.w, q1b.w);
            *(uint4*)(xd + cpi[1] * XHS + 4 * abi[1]) = w;
            w.x = pkh2(q2a.x, q2b.x); w.y = pkh2(q2a.y, q2b.y);
            w.z = pkh2(q2a.z, q2b.z); w.w = pkh2(q2a.w, q2b.w);
            *(uint4*)(xd + cpi[2] * XHS + 4 * abi[2]) = w;
            w.x = pkh2(q3a.x, q3b.x); w.y = pkh2(q3a.y, q3b.y);
            w.z = pkh2(q3a.z, q3b.z); w.w = pkh2(q3a.w, q3b.w);
            *(uint4*)(xd + cpi[3] * XHS + 4 * abi[3]) = w;
        }
        __syncthreads();            // sPart + X[g+1] visible; sC reads done

        // ---- tail: warp 0 softmax + min-max norm (overlaps next mma1) ----
        if (warp == 0) {
            const int a0 = lane, a1 = lane + 32;
            const float* pb0 = sPart[g & 1][0];
            const float* pb1 = sPart[g & 1][1];
            const float lg0 = tanhp(pb0[a0] + pb1[a0] + sba2[0]);
            const float lg1 = tanhp(pb0[a1] + pb1[a1] + sba2[0]);

            const unsigned m32 = 0xffffffffu;
            float mx = fmaxf(lg0, lg1);
            float mn = fminf(lg0, lg1);
            #pragma unroll
            for (int off = 16; off > 0; off >>= 1) {
                mx = fmaxf(mx, __shfl_xor_sync(m32, mx, off));
                mn = fminf(mn, __shfl_xor_sync(m32, mn, off));
            }
            const float e0 = expf(lg0 - mx);
            const float e1 = expf(lg1 - mx);
            float ssum = e0 + e1;
            #pragma unroll
            for (int off = 16; off > 0; off >>= 1) ssum += __shfl_xor_sync(m32, ssum, off);
            const float invs = 1.0f / ssum;

            const float w0  = e0 * invs;
            const float w1  = e1 * invs;
            const float wmn = expf(mn - mx) * invs;
            const float wmx = invs;
            const float kk  = (1.0f + 1e-6f) / (wmx - wmn + 1e-6f);

            float* ob = out + (size_t)gp * NAc;
            float* on = ob + (size_t)BZc * NUMc * NAc;
            ob[a0] = w0;
            ob[a1] = w1;
            on[a0] = kk * (w0 - wmn);
            on[a1] = kk * (w1 - wmn);
        }
    }
}

// ---------------- launch ----------------
extern "C" void kernel_launch(void* const* d_in, const int* in_sizes, int n_in,
                              void* d_out, int out_size)
{
    const float* loc  = (const float*)d_in[0];
    const float* feat = (const float*)d_in[1];

    disarm_prep<<<1, 256>>>(
        (const float*)d_in[2],  (const float*)d_in[3],  (const float*)d_in[4],  (const float*)d_in[5],
        (const float*)d_in[6],  (const float*)d_in[7],
        (const float*)d_in[8],  (const float*)d_in[9],  (const float*)d_in[10], (const float*)d_in[11],
        (const float*)d_in[12], (const float*)d_in[13], (const float*)d_in[14], (const float*)d_in[15],
        (const float*)d_in[16], (const float*)d_in[17],
        (const float*)d_in[18], (const float*)d_in[19], (const float*)d_in[20], (const float*)d_in[21],
        (const float*)d_in[22], (const float*)d_in[23]);

    static int smem_set = 0;
    if (!smem_set) {
        cudaFuncSetAttribute(disarm_mma,
                             cudaFuncAttributeMaxDynamicSharedMemorySize, SM_TOTAL);
        smem_set = 1;
    }
    disarm_mma<<<(BZc * NUMc) / GRPS, 256, SM_TOTAL>>>(loc, feat, (float*)d_out);
}